// round 7
// baseline (speedup 1.0000x reference)
#include <cuda_runtime.h>

// ElementwiseTensorProd_o1: l=1 outputs of per-channel tensor product.
//   p01_m = s_l * v_r[m]
//   p10_m = v_l[m] * s_r
//   p11_m = cross(v_l, v_r)[m] * (1/sqrt(2))
// Layout: inputs z0 (N,RANK), z1 (N,3,RANK); out (N,3,3*RANK) = [p01|p10|p11].
// R7: R6's block-phased R/W bursts with 512-thread blocks — doubles the
// same-direction burst length per barrier cohort (128KB read / 144KB write),
// halving DRAM bus-turnaround points per SM.

#define RANK 256
#define RQ   (RANK / 4)      // 64 float4 groups per rank row
#define OQ   (3 * RANK / 4)  // 192 float4 groups per output row
#define THREADS 512

__device__ __forceinline__ float4 mul4(float4 a, float4 b) {
    return make_float4(a.x * b.x, a.y * b.y, a.z * b.z, a.w * b.w);
}
__device__ __forceinline__ float4 fms4(float4 a, float4 b, float4 c, float4 d, float s) {
    return make_float4((a.x * b.x - c.x * d.x) * s,
                       (a.y * b.y - c.y * d.y) * s,
                       (a.z * b.z - c.z * d.z) * s,
                       (a.w * b.w - c.w * d.w) * s);
}

__global__ void __launch_bounds__(THREADS)
etp_o1_kernel(const float4* __restrict__ z0l,
              const float4* __restrict__ z1l,
              const float4* __restrict__ z0r,
              const float4* __restrict__ z1r,
              float4* __restrict__ out,
              int n_total)  // N * RQ
{
    const float INV_SQRT2 = 0.7071067811865476f;
    int idx = blockIdx.x * blockDim.x + threadIdx.x;
    bool active = (idx < n_total);
    if (!active) idx = n_total - 1;   // clamp: keep whole block in the barrier

    int n = idx >> 6;          // / RQ
    int r = idx & (RQ - 1);    // % RQ

    // ---- Load phase: whole block issues all 8 LDG.128 before any STG ----
    const float4* vl = z1l + (size_t)(n * 3) * RQ + r;
    const float4* vr = z1r + (size_t)(n * 3) * RQ + r;
    float4 sl  = __ldcs(z0l + (size_t)n * RQ + r);
    float4 sr  = __ldcs(z0r + (size_t)n * RQ + r);
    float4 vl0 = __ldcs(vl + 0 * RQ);
    float4 vl1 = __ldcs(vl + 1 * RQ);
    float4 vl2 = __ldcs(vl + 2 * RQ);
    float4 vr0 = __ldcs(vr + 0 * RQ);
    float4 vr1 = __ldcs(vr + 1 * RQ);
    float4 vr2 = __ldcs(vr + 2 * RQ);

    // Cohort the phases: no warp starts its store burst until every warp
    // in the block has issued its load burst.
    __syncthreads();

    if (!active) return;

    // ---- Store phase: 9x STG.128 burst ----
    float4* ob = out + (size_t)(n * 3) * OQ + r;

    // m = 0
    __stcs(ob + 0 * OQ + 0 * RQ, mul4(sl, vr0));
    __stcs(ob + 0 * OQ + 1 * RQ, mul4(vl0, sr));
    __stcs(ob + 0 * OQ + 2 * RQ, fms4(vl1, vr2, vl2, vr1, INV_SQRT2));
    // m = 1
    __stcs(ob + 1 * OQ + 0 * RQ, mul4(sl, vr1));
    __stcs(ob + 1 * OQ + 1 * RQ, mul4(vl1, sr));
    __stcs(ob + 1 * OQ + 2 * RQ, fms4(vl2, vr0, vl0, vr2, INV_SQRT2));
    // m = 2
    __stcs(ob + 2 * OQ + 0 * RQ, mul4(sl, vr2));
    __stcs(ob + 2 * OQ + 1 * RQ, mul4(vl2, sr));
    __stcs(ob + 2 * OQ + 2 * RQ, fms4(vl0, vr1, vl1, vr0, INV_SQRT2));
}

extern "C" void kernel_launch(void* const* d_in, const int* in_sizes, int n_in,
                              void* d_out, int out_size) {
    const float4* z0l = (const float4*)d_in[0];
    const float4* z1l = (const float4*)d_in[1];
    const float4* z0r = (const float4*)d_in[2];
    const float4* z1r = (const float4*)d_in[3];
    float4* out = (float4*)d_out;

    int N = in_sizes[0] / RANK;          // 50000
    int n_total = N * RQ;                // 3.2M float4-work-items
    int blocks = (n_total + THREADS - 1) / THREADS;
    etp_o1_kernel<<<blocks, THREADS>>>(z0l, z1l, z0r, z1r, out, n_total);
}

// round 8
// speedup vs baseline: 1.0098x; 1.0098x over previous
#include <cuda_runtime.h>

// ElementwiseTensorProd_o1: l=1 outputs of per-channel tensor product.
//   p01_m = s_l * v_r[m]
//   p10_m = v_l[m] * s_r
//   p11_m = cross(v_l, v_r)[m] * (1/sqrt(2))
// Layout: inputs z0 (N,RANK), z1 (N,3,RANK); out (N,3,3*RANK) = [p01|p10|p11].
// R8: block-phased R/W bursts with 1024-thread blocks — 256KB read / 288KB
// write per barrier cohort. Cohort-size scaling showed monotone DRAM-efficiency
// gains (256t: 84.0%, 512t: 84.4%); this doubles burst length once more.

#define RANK 256
#define RQ   (RANK / 4)      // 64 float4 groups per rank row
#define OQ   (3 * RANK / 4)  // 192 float4 groups per output row
#define THREADS 1024

__device__ __forceinline__ float4 mul4(float4 a, float4 b) {
    return make_float4(a.x * b.x, a.y * b.y, a.z * b.z, a.w * b.w);
}
__device__ __forceinline__ float4 fms4(float4 a, float4 b, float4 c, float4 d, float s) {
    return make_float4((a.x * b.x - c.x * d.x) * s,
                       (a.y * b.y - c.y * d.y) * s,
                       (a.z * b.z - c.z * d.z) * s,
                       (a.w * b.w - c.w * d.w) * s);
}

__global__ void __launch_bounds__(THREADS)
etp_o1_kernel(const float4* __restrict__ z0l,
              const float4* __restrict__ z1l,
              const float4* __restrict__ z0r,
              const float4* __restrict__ z1r,
              float4* __restrict__ out,
              int n_total)  // N * RQ
{
    const float INV_SQRT2 = 0.7071067811865476f;
    int idx = blockIdx.x * blockDim.x + threadIdx.x;
    bool active = (idx < n_total);
    if (!active) idx = n_total - 1;   // clamp: keep whole block in the barrier

    int n = idx >> 6;          // / RQ
    int r = idx & (RQ - 1);    // % RQ

    // ---- Load phase: whole block issues all 8 LDG.128 before any STG ----
    const float4* vl = z1l + (size_t)(n * 3) * RQ + r;
    const float4* vr = z1r + (size_t)(n * 3) * RQ + r;
    float4 sl  = __ldcs(z0l + (size_t)n * RQ + r);
    float4 sr  = __ldcs(z0r + (size_t)n * RQ + r);
    float4 vl0 = __ldcs(vl + 0 * RQ);
    float4 vl1 = __ldcs(vl + 1 * RQ);
    float4 vl2 = __ldcs(vl + 2 * RQ);
    float4 vr0 = __ldcs(vr + 0 * RQ);
    float4 vr1 = __ldcs(vr + 1 * RQ);
    float4 vr2 = __ldcs(vr + 2 * RQ);

    // Cohort the phases: no warp starts its store burst until every warp
    // in the block has issued its load burst.
    __syncthreads();

    if (!active) return;

    // ---- Store phase: 9x STG.128 burst ----
    float4* ob = out + (size_t)(n * 3) * OQ + r;

    // m = 0
    __stcs(ob + 0 * OQ + 0 * RQ, mul4(sl, vr0));
    __stcs(ob + 0 * OQ + 1 * RQ, mul4(vl0, sr));
    __stcs(ob + 0 * OQ + 2 * RQ, fms4(vl1, vr2, vl2, vr1, INV_SQRT2));
    // m = 1
    __stcs(ob + 1 * OQ + 0 * RQ, mul4(sl, vr1));
    __stcs(ob + 1 * OQ + 1 * RQ, mul4(vl1, sr));
    __stcs(ob + 1 * OQ + 2 * RQ, fms4(vl2, vr0, vl0, vr2, INV_SQRT2));
    // m = 2
    __stcs(ob + 2 * OQ + 0 * RQ, mul4(sl, vr2));
    __stcs(ob + 2 * OQ + 1 * RQ, mul4(vl2, sr));
    __stcs(ob + 2 * OQ + 2 * RQ, fms4(vl0, vr1, vl1, vr0, INV_SQRT2));
}

extern "C" void kernel_launch(void* const* d_in, const int* in_sizes, int n_in,
                              void* d_out, int out_size) {
    const float4* z0l = (const float4*)d_in[0];
    const float4* z1l = (const float4*)d_in[1];
    const float4* z0r = (const float4*)d_in[2];
    const float4* z1r = (const float4*)d_in[3];
    float4* out = (float4*)d_out;

    int N = in_sizes[0] / RANK;          // 50000
    int n_total = N * RQ;                // 3.2M float4-work-items
    int blocks = (n_total + THREADS - 1) / THREADS;
    etp_o1_kernel<<<blocks, THREADS>>>(z0l, z1l, z0r, z1r, out, n_total);
}